// round 11
// baseline (speedup 1.0000x reference)
#include <cuda_runtime.h>
#include <cuda_fp16.h>
#include <math.h>
#include <stdint.h>

#define BB 8
#define RR 128
#define TS 16384
#define NL 9
#define NTHR 256

// operand tiles: packed half2 words, [kpair][t-permuted], 64-t tile, pitch 72 words.
// N-permutation within each 32-col block: col t stored at (t&7)*4 + ((t>>3)&3)
// so B-fragment quads are contiguous (LDS.128).
#define PT 72

// ---- global scratch ----
__device__ __align__(16) float g_h[2][(size_t)BB * RR * TS];
__device__ __align__(16) float g_skip[(size_t)BB * RR * TS];
// fragment-permuted fp16 weights, hi/lo split (3-term scheme)
__device__ __align__(16) __half g_w1h[NL * 12 * 8192];
__device__ __align__(16) __half g_w1l[NL * 12 * 8192];
__device__ __align__(16) __half g_w2h[NL * 4 * 8192];
__device__ __align__(16) __half g_w2l[NL * 4 * 8192];

__constant__ int c_dil[NL] = {1, 2, 4, 8, 16, 32, 64, 128, 256};

__device__ __forceinline__ float sigmoidf_(float x) { return 1.f / (1.f + __expf(-x)); }

__device__ __forceinline__ void mma16(float* d, uint4 a, uint32_t b0, uint32_t b1) {
    asm volatile("mma.sync.aligned.m16n8k16.row.col.f32.f16.f16.f32 "
                 "{%0,%1,%2,%3}, {%4,%5,%6,%7}, {%8,%9}, {%0,%1,%2,%3};"
                 : "+f"(d[0]), "+f"(d[1]), "+f"(d[2]), "+f"(d[3])
                 : "r"(a.x), "r"(a.y), "r"(a.z), "r"(a.w), "r"(b0), "r"(b1));
}

// pack 2 fp32 into hi/lo half2 words
__device__ __forceinline__ void mkb(float v0, float v1, uint32_t& bh, uint32_t& bl) {
    __half h0 = __float2half_rn(v0), h1 = __float2half_rn(v1);
    __half l0 = __float2half_rn(v0 - __half2float(h0));
    __half l1 = __float2half_rn(v1 - __half2float(h1));
    __half2 ph = __halves2half2(h0, h1), pl = __halves2half2(l0, l1);
    bh = *(uint32_t*)&ph;
    bl = *(uint32_t*)&pl;
}

// permuted column position within a 64-col tile
__device__ __forceinline__ int permc(int t) {
    return (t & 32) + ((t & 7) << 2) + ((t >> 3) & 3);
}

// A-frag (f16 m16n8k16) element e in 0..7:  row = g + ((e>>1)&1)*8 ;  k = 2q + (e&1) + (e>>2)*8
// oc mapping: mt 0,1 -> low half, mt 2,3 -> +128.
__global__ void k_prep(const float* __restrict__ conv_w,
                       const float* __restrict__ out_w,
                       const float* __restrict__ out1_w) {
    int i = blockIdx.x * blockDim.x + threadIdx.x;
    const int n1 = NL * 12 * 8192;
    const int n2 = NL * 4 * 8192;
    if (i < n1) {
        int j = i & 8191;
        int ci = i >> 13;            // (l*3+tap)*4 + kc
        int kc = ci & 3;
        int tap = (ci >> 2) % 3;
        int l = ci / 12;
        int e = j & 7, lane = (j >> 3) & 31, mt = (j >> 8) & 3, ks = (j >> 10) & 1, og = (j >> 11) & 3;
        int g = lane >> 2, q = lane & 3;
        int oc = og * 32 + (mt & 1) * 16 + (mt >> 1) * 128 + g + ((e >> 1) & 1) * 8;
        int r = kc * 32 + ks * 16 + 2 * q + (e & 1) + (e >> 2) * 8;
        float w = conv_w[((l * 256 + oc) * 128 + r) * 3 + tap];
        __half hi = __float2half_rn(w);
        g_w1h[i] = hi;
        g_w1l[i] = __float2half_rn(w - __half2float(hi));
    } else if (i < n1 + n2) {
        int ii = i - n1;
        int j = ii & 8191;
        int ci = ii >> 13;           // l*4 + kc
        int kc = ci & 3;
        int l = ci >> 2;
        int e = j & 7, lane = (j >> 3) & 31, mt = (j >> 8) & 3, ks = (j >> 10) & 1, og = (j >> 11) & 3;
        int g = lane >> 2, q = lane & 3;
        int m = og * 32 + (mt & 1) * 16 + (mt >> 1) * 128 + g + ((e >> 1) & 1) * 8;
        // phase-2 K is permuted: slot 2s -> ch (s>>4)*32+((s>>3)&1)*16+(s&7); slot 2s+1 -> +8
        int k = kc * 32 + ks * 16 + 2 * q + (e & 1) + (e >> 2) * 8;
        int s = k >> 1, odd = k & 1;
        int r = (s >> 4) * 32 + ((s >> 3) & 1) * 16 + (s & 7) + odd * 8;
        float w;
        if (m < 128) w = out_w[(l * 128 + m) * 128 + r];
        else         w = out1_w[(m - 128) * (RR * NL) + l * 128 + r];
        __half hi = __float2half_rn(w);
        g_w2h[ii] = hi;
        g_w2l[ii] = __float2half_rn(w - __half2float(hi));
    }
}

__global__ void k_input(const float* __restrict__ x, const float* __restrict__ iw,
                        const float* __restrict__ ib, const float* __restrict__ ob1) {
    size_t idx = (size_t)blockIdx.x * blockDim.x + threadIdx.x;
    int t = (int)(idx % TS);
    size_t br = idx / TS;
    int r = (int)(br % RR);
    int b = (int)(br / RR);
    float v = tanhf(iw[r] * x[(size_t)b * TS + t] + ib[r]);
    g_h[0][idx] = v;
    g_skip[idx] = ob1[r];
}

// SMEM word offsets (words)
#define OAH0 0u
#define OAL0 1152u
#define OAH1 2304u
#define OAL1 3456u
#define OZH  4608u
#define OZL  9216u
#define OCB  13824u
#define OOB  14080u
#define SMW  14208u

__global__ __launch_bounds__(NTHR, 2)
void k_layer(int l, int parity,
             const float* __restrict__ conv_b, const float* __restrict__ out_b) {
    extern __shared__ __align__(16) uint32_t sw[];
    float* cb = (float*)(sw + OCB);
    float* ob = (float*)(sw + OOB);

    const int tid = threadIdx.x;
    const int lane = tid & 31;
    const int wid = tid >> 5;
    const int wm = wid >> 1;          // oc group 0..3
    const int wn = wid & 1;           // t group 0..1
    const int g = lane >> 2;
    const int q = lane & 3;

    const int b = blockIdx.y;
    const int t0 = blockIdx.x * 64;
    const int dil = c_dil[l];

    const float* __restrict__ hin = g_h[parity] + (size_t)b * RR * TS;
    float* __restrict__ hout = g_h[parity ^ 1] + (size_t)b * RR * TS;
    float* __restrict__ skp = g_skip + (size_t)b * RR * TS;

    if (tid < 256) cb[tid] = conv_b[l * 256 + tid];
    if (tid < 128) ob[tid] = out_b[l * 128 + tid];

    // fill mapping: thread owns kpair kp (rows 2kp,2kp+1) x 4 t (tg + j*16)
    const int kp = tid >> 4;          // 0..15
    const int tg = tid & 15;

    float acc[4][4][4];
#pragma unroll
    for (int mt = 0; mt < 4; mt++)
#pragma unroll
        for (int nt = 0; nt < 4; nt++)
#pragma unroll
            for (int e = 0; e < 4; e++) acc[mt][nt][e] = 0.f;

    // ---- prologue: fill chunk 0 into buf0 (N-permuted) ----
    {
        int shift = -2 * dil;            // tap 0, kc 0
        const float* r0p = hin + (size_t)(2 * kp) * TS + t0 + shift;
        const float* r1p = r0p + TS;
#pragma unroll
        for (int j = 0; j < 4; j++) {
            int t = tg + j * 16;
            int tb = t0 + shift + t;
            float v0 = (tb >= 0) ? r0p[t] : 0.f;
            float v1 = (tb >= 0) ? r1p[t] : 0.f;
            uint32_t hw, lw;
            mkb(v0, v1, hw, lw);
            int p = permc(t);
            sw[OAH0 + kp * PT + p] = hw;
            sw[OAL0 + kp * PT + p] = lw;
        }
    }
    __syncthreads();

    // ---- phase 1: D1[256 oc][64 t], K = 384 (12 chunks of 32) ----
    for (int c = 0; c < 12; c++) {
        float pv0[4], pv1[4];
        const int have = (c < 11);
        if (have) {
            int c2 = c + 1;
            int tap2 = c2 >> 2, kc2 = c2 & 3;
            int shift = (tap2 - 2) * dil;
            const float* r0p = hin + (size_t)(kc2 * 32 + 2 * kp) * TS + t0 + shift;
            const float* r1p = r0p + TS;
#pragma unroll
            for (int j = 0; j < 4; j++) {
                int t = tg + j * 16;
                int tb = t0 + shift + t;
                pv0[j] = (tb >= 0) ? r0p[t] : 0.f;
                pv1[j] = (tb >= 0) ? r1p[t] : 0.f;
            }
        }

        size_t choff = ((size_t)((l * 3 + (c >> 2)) * 4 + (c & 3))) * 8192 + wm * 2048;
        const __half* wh = g_w1h + choff;
        const __half* wl = g_w1l + choff;
        const uint32_t* bh = sw + ((c & 1) ? OAH1 : OAH0);
        const uint32_t* bl = sw + ((c & 1) ? OAL1 : OAL0);
#pragma unroll
        for (int ks = 0; ks < 2; ks++) {
            uint32_t base = (uint32_t)(ks * 8 + q) * PT + wn * 32 + g * 4;
            uint4 vh0 = *(const uint4*)(bh + base);
            uint4 vh1 = *(const uint4*)(bh + base + 4 * PT);
            uint4 vl0 = *(const uint4*)(bl + base);
            uint4 vl1 = *(const uint4*)(bl + base + 4 * PT);
            uint32_t b0h[4] = {vh0.x, vh0.y, vh0.z, vh0.w};
            uint32_t b1h[4] = {vh1.x, vh1.y, vh1.z, vh1.w};
            uint32_t b0l[4] = {vl0.x, vl0.y, vl0.z, vl0.w};
            uint32_t b1l[4] = {vl1.x, vl1.y, vl1.z, vl1.w};
#pragma unroll
            for (int mt = 0; mt < 4; mt++) {
                uint4 ah = ((const uint4*)(wh + ks * 1024 + mt * 256))[lane];
                uint4 al = ((const uint4*)(wl + ks * 1024 + mt * 256))[lane];
#pragma unroll
                for (int nt = 0; nt < 4; nt++) {
                    mma16(acc[mt][nt], ah, b0h[nt], b1h[nt]);
                    mma16(acc[mt][nt], ah, b0l[nt], b1l[nt]);
                    mma16(acc[mt][nt], al, b0h[nt], b1h[nt]);
                }
            }
        }

        if (have) {
            uint32_t dh = ((c + 1) & 1) ? OAH1 : OAH0;
            uint32_t dl = ((c + 1) & 1) ? OAL1 : OAL0;
#pragma unroll
            for (int j = 0; j < 4; j++) {
                int t = tg + j * 16;
                uint32_t hw, lw;
                mkb(pv0[j], pv1[j], hw, lw);
                int p = permc(t);
                sw[dh + kp * PT + p] = hw;
                sw[dl + kp * PT + p] = lw;
            }
        }
        __syncthreads();
    }

    // ---- epilogue 1: gate -> z tile (half2 hi/lo, K-pair (zc,zc+8), N-permuted) ----
#pragma unroll
    for (int mt = 0; mt < 2; mt++) {
        int zc = wm * 32 + mt * 16 + g;
        int s = wm * 16 + mt * 8 + g;     // kpair slot
        float bt0 = cb[zc], bg0 = cb[128 + zc];
        float bt8 = cb[zc + 8], bg8 = cb[128 + zc + 8];
#pragma unroll
        for (int nt = 0; nt < 4; nt++) {
            float zA0 = tanhf(acc[mt][nt][0] + bt0) * sigmoidf_(acc[mt + 2][nt][0] + bg0);
            float zA1 = tanhf(acc[mt][nt][1] + bt0) * sigmoidf_(acc[mt + 2][nt][1] + bg0);
            float zB0 = tanhf(acc[mt][nt][2] + bt8) * sigmoidf_(acc[mt + 2][nt][2] + bg8);
            float zB1 = tanhf(acc[mt][nt][3] + bt8) * sigmoidf_(acc[mt + 2][nt][3] + bg8);
            // cols tc = wn*32 + nt*8 + 2q and tc+1, permuted: wn*32 + 8q + nt (+4)
            int p0 = wn * 32 + 8 * q + nt;
            uint32_t hw, lw;
            mkb(zA0, zB0, hw, lw);
            sw[OZH + s * PT + p0] = hw;
            sw[OZL + s * PT + p0] = lw;
            mkb(zA1, zB1, hw, lw);
            sw[OZH + s * PT + p0 + 4] = hw;
            sw[OZL + s * PT + p0 + 4] = lw;
        }
    }
    __syncthreads();

    // ---- phase 2: [res;skip][t] = W2 @ z (K permuted), K = 128 ----
#pragma unroll
    for (int mt = 0; mt < 4; mt++)
#pragma unroll
        for (int nt = 0; nt < 4; nt++)
#pragma unroll
            for (int e = 0; e < 4; e++) acc[mt][nt][e] = 0.f;

    for (int kc = 0; kc < 4; kc++) {
        size_t choff = (size_t)(l * 4 + kc) * 8192 + wm * 2048;
        const __half* wh = g_w2h + choff;
        const __half* wl = g_w2l + choff;
#pragma unroll
        for (int ks = 0; ks < 2; ks++) {
            uint32_t base = (uint32_t)(kc * 16 + ks * 8 + q) * PT + wn * 32 + g * 4;
            uint4 vh0 = *(const uint4*)(sw + OZH + base);
            uint4 vh1 = *(const uint4*)(sw + OZH + base + 4 * PT);
            uint4 vl0 = *(const uint4*)(sw + OZL + base);
            uint4 vl1 = *(const uint4*)(sw + OZL + base + 4 * PT);
            uint32_t b0h[4] = {vh0.x, vh0.y, vh0.z, vh0.w};
            uint32_t b1h[4] = {vh1.x, vh1.y, vh1.z, vh1.w};
            uint32_t b0l[4] = {vl0.x, vl0.y, vl0.z, vl0.w};
            uint32_t b1l[4] = {vl1.x, vl1.y, vl1.z, vl1.w};
#pragma unroll
            for (int mt = 0; mt < 4; mt++) {
                uint4 ah = ((const uint4*)(wh + ks * 1024 + mt * 256))[lane];
                uint4 al = ((const uint4*)(wl + ks * 1024 + mt * 256))[lane];
#pragma unroll
                for (int nt = 0; nt < 4; nt++) {
                    mma16(acc[mt][nt], ah, b0h[nt], b1h[nt]);
                    mma16(acc[mt][nt], ah, b0l[nt], b1l[nt]);
                    mma16(acc[mt][nt], al, b0h[nt], b1h[nt]);
                }
            }
        }
    }

    // ---- epilogue 2: h_out = h_in + res + out_b ; skip += delta ----
#pragma unroll
    for (int mt = 0; mt < 2; mt++) {
        int r0 = wm * 32 + mt * 16 + g;
        float ob0 = ob[r0], ob8 = ob[r0 + 8];
#pragma unroll
        for (int nt = 0; nt < 4; nt++) {
            int tc = wn * 32 + nt * 8 + 2 * q;
            size_t ix = (size_t)r0 * TS + t0 + tc;
            size_t ix8 = ix + (size_t)8 * TS;

            float2 hv = *(const float2*)(hin + ix);
            *(float2*)(hout + ix) = make_float2(hv.x + acc[mt][nt][0] + ob0,
                                                hv.y + acc[mt][nt][1] + ob0);
            float2 hv8 = *(const float2*)(hin + ix8);
            *(float2*)(hout + ix8) = make_float2(hv8.x + acc[mt][nt][2] + ob8,
                                                 hv8.y + acc[mt][nt][3] + ob8);

            float2 sv = *(const float2*)(skp + ix);
            sv.x += acc[mt + 2][nt][0];
            sv.y += acc[mt + 2][nt][1];
            *(float2*)(skp + ix) = sv;
            float2 sv8 = *(const float2*)(skp + ix8);
            sv8.x += acc[mt + 2][nt][2];
            sv8.y += acc[mt + 2][nt][3];
            *(float2*)(skp + ix8) = sv8;
        }
    }
}

__global__ void k_out(const float* __restrict__ w2, const float* __restrict__ b2,
                      float* __restrict__ out) {
    int idx = blockIdx.x * blockDim.x + threadIdx.x;  // b*T + t
    int t = idx % TS;
    int b = idx / TS;
    const float* sp = g_skip + (size_t)b * RR * TS + t;
    float a = 0.f;
#pragma unroll 8
    for (int ro = 0; ro < RR; ro++) a += w2[ro] * tanhf(sp[(size_t)ro * TS]);
    out[idx] = a + b2[0];
}

extern "C" void kernel_launch(void* const* d_in, const int* in_sizes, int n_in,
                              void* d_out, int out_size) {
    const float* x       = (const float*)d_in[0];
    const float* input_w = (const float*)d_in[1];
    const float* input_b = (const float*)d_in[2];
    const float* conv_w  = (const float*)d_in[3];
    const float* conv_b  = (const float*)d_in[4];
    const float* out_w   = (const float*)d_in[5];
    const float* out_b   = (const float*)d_in[6];
    const float* out1_w  = (const float*)d_in[7];
    const float* out1_b  = (const float*)d_in[8];
    const float* out2_w  = (const float*)d_in[9];
    const float* out2_b  = (const float*)d_in[10];

    const int SMEM = SMW * 4;  // 56832 bytes -> 2 CTAs/SM
    cudaFuncSetAttribute(k_layer, cudaFuncAttributeMaxDynamicSharedMemorySize, SMEM);

    int n_prep = NL * 12 * 8192 + NL * 4 * 8192;
    k_prep<<<(n_prep + 255) / 256, 256>>>(conv_w, out_w, out1_w);
    k_input<<<(BB * RR * TS) / 256, 256>>>(x, input_w, input_b, out1_b);

    int par = 0;
    for (int l = 0; l < NL; l++) {
        k_layer<<<dim3(TS / 64, BB), NTHR, SMEM>>>(l, par, conv_b, out_b);
        par ^= 1;
    }
    k_out<<<(BB * TS) / 256, 256>>>(out2_w, out2_b, (float*)d_out);
}

// round 12
// speedup vs baseline: 1.2057x; 1.2057x over previous
#include <cuda_runtime.h>
#include <cuda_fp16.h>
#include <math.h>
#include <stdint.h>

#define BB 8
#define RR 128
#define TS 16384
#define NL 9
#define NTHR 256
#define PT 72   // operand tile pitch (words); [kpair][t], 64-t tile

// ---- global scratch ----
__device__ __align__(16) float    g_hf[2][(size_t)BB * RR * TS];   // fp32 residual stream
__device__ __align__(16) uint32_t g_hh[2][(size_t)BB * 64 * TS];   // half2-hi words [b][kpair][t]
__device__ __align__(16) uint32_t g_hl[2][(size_t)BB * 64 * TS];   // half2-lo words
__device__ __align__(16) float    g_skip[(size_t)BB * RR * TS];
__device__ __align__(16) __half g_w1h[NL * 12 * 8192];
__device__ __align__(16) __half g_w1l[NL * 12 * 8192];
__device__ __align__(16) __half g_w2h[NL * 4 * 8192];
__device__ __align__(16) __half g_w2l[NL * 4 * 8192];

__constant__ int c_dil[NL] = {1, 2, 4, 8, 16, 32, 64, 128, 256};

// MUFU-based sigmoid/tanh (~2^-22 accurate)
__device__ __forceinline__ float fsig(float x) {
    float e, r;
    asm("ex2.approx.f32 %0, %1;" : "=f"(e) : "f"(-1.4426950408889634f * x));
    asm("rcp.approx.f32 %0, %1;" : "=f"(r) : "f"(1.f + e));
    return r;
}
__device__ __forceinline__ float ftanh(float x) { return 2.f * fsig(2.f * x) - 1.f; }

__device__ __forceinline__ void mma16(float* d, uint4 a, uint32_t b0, uint32_t b1) {
    asm volatile("mma.sync.aligned.m16n8k16.row.col.f32.f16.f16.f32 "
                 "{%0,%1,%2,%3}, {%4,%5,%6,%7}, {%8,%9}, {%0,%1,%2,%3};"
                 : "+f"(d[0]), "+f"(d[1]), "+f"(d[2]), "+f"(d[3])
                 : "r"(a.x), "r"(a.y), "r"(a.z), "r"(a.w), "r"(b0), "r"(b1));
}

__device__ __forceinline__ void mkb(float v0, float v1, uint32_t& bh, uint32_t& bl) {
    __half h0 = __float2half_rn(v0), h1 = __float2half_rn(v1);
    __half l0 = __float2half_rn(v0 - __half2float(h0));
    __half l1 = __float2half_rn(v1 - __half2float(h1));
    __half2 ph = __halves2half2(h0, h1), pl = __halves2half2(l0, l1);
    bh = *(uint32_t*)&ph;
    bl = *(uint32_t*)&pl;
}

__device__ __forceinline__ void cpa4(uint32_t daddr, const void* src, int size) {
    asm volatile("cp.async.ca.shared.global [%0], [%1], 4, %2;"
                 :: "r"(daddr), "l"(src), "r"(size) : "memory");
}

// A-frag (f16 m16n8k16) element e in 0..7:  row = g + ((e>>1)&1)*8 ;  k = 2q + (e&1) + (e>>2)*8
__global__ void k_prep(const float* __restrict__ conv_w,
                       const float* __restrict__ out_w,
                       const float* __restrict__ out1_w) {
    int i = blockIdx.x * blockDim.x + threadIdx.x;
    const int n1 = NL * 12 * 8192;
    const int n2 = NL * 4 * 8192;
    if (i < n1) {
        int j = i & 8191;
        int ci = i >> 13;            // (l*3+tap)*4 + kc
        int kc = ci & 3;
        int tap = (ci >> 2) % 3;
        int l = ci / 12;
        int e = j & 7, lane = (j >> 3) & 31, mt = (j >> 8) & 3, ks = (j >> 10) & 1, og = (j >> 11) & 3;
        int g = lane >> 2, q = lane & 3;
        int oc = og * 32 + (mt & 1) * 16 + (mt >> 1) * 128 + g + ((e >> 1) & 1) * 8;
        int r = kc * 32 + ks * 16 + 2 * q + (e & 1) + (e >> 2) * 8;
        float w = conv_w[((l * 256 + oc) * 128 + r) * 3 + tap];
        __half hi = __float2half_rn(w);
        g_w1h[i] = hi;
        g_w1l[i] = __float2half_rn(w - __half2float(hi));
    } else if (i < n1 + n2) {
        int ii = i - n1;
        int j = ii & 8191;
        int ci = ii >> 13;           // l*4 + kc
        int kc = ci & 3;
        int l = ci >> 2;
        int e = j & 7, lane = (j >> 3) & 31, mt = (j >> 8) & 3, ks = (j >> 10) & 1, og = (j >> 11) & 3;
        int g = lane >> 2, q = lane & 3;
        int m = og * 32 + (mt & 1) * 16 + (mt >> 1) * 128 + g + ((e >> 1) & 1) * 8;
        // phase-2 K permuted: slot 2s -> ch (s>>4)*32+((s>>3)&1)*16+(s&7); slot 2s+1 -> +8
        int k = kc * 32 + ks * 16 + 2 * q + (e & 1) + (e >> 2) * 8;
        int s = k >> 1, odd = k & 1;
        int r = (s >> 4) * 32 + ((s >> 3) & 1) * 16 + (s & 7) + odd * 8;
        float w;
        if (m < 128) w = out_w[(l * 128 + m) * 128 + r];
        else         w = out1_w[(m - 128) * (RR * NL) + l * 128 + r];
        __half hi = __float2half_rn(w);
        g_w2h[ii] = hi;
        g_w2l[ii] = __float2half_rn(w - __half2float(hi));
    }
}

// input layer: thread per (b, kpair, t)
__global__ void k_input(const float* __restrict__ x, const float* __restrict__ iw,
                        const float* __restrict__ ib, const float* __restrict__ ob1) {
    size_t idx = (size_t)blockIdx.x * blockDim.x + threadIdx.x;
    int t = (int)(idx & (TS - 1));
    int kp = (int)((idx >> 14) & 63);
    int b = (int)(idx >> 20);
    float xv = x[(size_t)b * TS + t];
    int r0 = 2 * kp;
    float v0 = ftanh(iw[r0] * xv + ib[r0]);
    float v1 = ftanh(iw[r0 + 1] * xv + ib[r0 + 1]);
    size_t ix0 = ((size_t)b * RR + r0) * TS + t;
    g_hf[0][ix0] = v0;
    g_hf[0][ix0 + TS] = v1;
    g_skip[ix0] = ob1[r0];
    g_skip[ix0 + TS] = ob1[r0 + 1];
    uint32_t hw, lw;
    mkb(v0, v1, hw, lw);
    size_t px = ((size_t)b * 64 + kp) * TS + t;
    g_hh[0][px] = hw;
    g_hl[0][px] = lw;
}

// SMEM word offsets
#define OAH0 0u
#define OAL0 1152u
#define OAH1 2304u
#define OAL1 3456u
#define OZH  4608u
#define OZL  9216u
#define OCB  13824u
#define OOB  14080u
#define SMW  14208u

__global__ __launch_bounds__(NTHR, 2)
void k_layer(int l, int parity,
             const float* __restrict__ conv_b, const float* __restrict__ out_b) {
    extern __shared__ __align__(16) uint32_t sw[];
    float* cb = (float*)(sw + OCB);
    float* ob = (float*)(sw + OOB);
    uint32_t sbase = (uint32_t)__cvta_generic_to_shared(sw);

    const int tid = threadIdx.x;
    const int lane = tid & 31;
    const int wid = tid >> 5;
    const int wm = wid >> 1;          // oc group 0..3
    const int wn = wid & 1;           // t group 0..1
    const int g = lane >> 2;
    const int q = lane & 3;
    const int tcb = wn * 32 + g;

    const int b = blockIdx.y;
    const int t0 = blockIdx.x * 64;
    const int dil = c_dil[l];

    const float* __restrict__ hfin = g_hf[parity] + (size_t)b * RR * TS;
    float* __restrict__ hfout = g_hf[parity ^ 1] + (size_t)b * RR * TS;
    const uint32_t* __restrict__ hhin = g_hh[parity] + (size_t)b * 64 * TS;
    const uint32_t* __restrict__ hlin = g_hl[parity] + (size_t)b * 64 * TS;
    uint32_t* __restrict__ hhout = g_hh[parity ^ 1] + (size_t)b * 64 * TS;
    uint32_t* __restrict__ hlout = g_hl[parity ^ 1] + (size_t)b * 64 * TS;
    float* __restrict__ skp = g_skip + (size_t)b * RR * TS;

    cb[tid] = conv_b[l * 256 + tid];
    if (tid < 128) ob[tid] = out_b[l * 128 + tid];

    const int kp = tid >> 4;          // fill kpair 0..15
    const int tg = tid & 15;

    float acc[4][4][4];
#pragma unroll
    for (int mt = 0; mt < 4; mt++)
#pragma unroll
        for (int nt = 0; nt < 4; nt++)
#pragma unroll
            for (int e = 0; e < 4; e++) acc[mt][nt][e] = 0.f;

    // ---- issue cp.async fill for chunk 0 ----
    {
        int shift = -2 * dil;
        const uint32_t* sH = hhin + (size_t)kp * TS;
        const uint32_t* sL = hlin + (size_t)kp * TS;
        uint32_t dH = sbase + 4u * (OAH0 + kp * PT);
        uint32_t dL = sbase + 4u * (OAL0 + kp * PT);
#pragma unroll
        for (int j = 0; j < 4; j++) {
            int t = tg + j * 16;
            int tb = t0 + shift + t;
            int sz = (tb >= 0) ? 4 : 0;
            int so = (tb >= 0) ? tb : 0;
            cpa4(dH + 4u * t, sH + so, sz);
            cpa4(dL + 4u * t, sL + so, sz);
        }
        asm volatile("cp.async.commit_group;" ::: "memory");
    }
    asm volatile("cp.async.wait_group 0;" ::: "memory");
    __syncthreads();

    // ---- phase 1: D1[256 oc][64 t], K = 384 (12 chunks) ----
    for (int c = 0; c < 12; c++) {
        if (c < 11) {
            int c2 = c + 1;
            int tap2 = c2 >> 2, kc2 = c2 & 3;
            int shift = (tap2 - 2) * dil;
            const uint32_t* sH = hhin + (size_t)(kc2 * 16 + kp) * TS;
            const uint32_t* sL = hlin + (size_t)(kc2 * 16 + kp) * TS;
            uint32_t bo = (c2 & 1) ? OAH1 : OAH0;
            uint32_t bl2 = (c2 & 1) ? OAL1 : OAL0;
            uint32_t dH = sbase + 4u * (bo + kp * PT);
            uint32_t dL = sbase + 4u * (bl2 + kp * PT);
#pragma unroll
            for (int j = 0; j < 4; j++) {
                int t = tg + j * 16;
                int tb = t0 + shift + t;
                int sz = (tb >= 0) ? 4 : 0;
                int so = (tb >= 0) ? tb : 0;
                cpa4(dH + 4u * t, sH + so, sz);
                cpa4(dL + 4u * t, sL + so, sz);
            }
            asm volatile("cp.async.commit_group;" ::: "memory");
        }

        size_t choff = ((size_t)((l * 3 + (c >> 2)) * 4 + (c & 3))) * 8192 + wm * 2048;
        const __half* wh = g_w1h + choff;
        const __half* wl = g_w1l + choff;
        const uint32_t* bh = sw + ((c & 1) ? OAH1 : OAH0);
        const uint32_t* blw = sw + ((c & 1) ? OAL1 : OAL0);
#pragma unroll
        for (int ks = 0; ks < 2; ks++) {
            uint32_t base = (uint32_t)(ks * 8 + q) * PT + tcb;
            uint32_t b0h[4], b0l[4], b1h[4], b1l[4];
#pragma unroll
            for (int nt = 0; nt < 4; nt++) {
                b0h[nt] = bh[base + nt * 8];
                b1h[nt] = bh[base + 4 * PT + nt * 8];
                b0l[nt] = blw[base + nt * 8];
                b1l[nt] = blw[base + 4 * PT + nt * 8];
            }
#pragma unroll
            for (int mt = 0; mt < 4; mt++) {
                uint4 ah = ((const uint4*)(wh + ks * 1024 + mt * 256))[lane];
                uint4 al = ((const uint4*)(wl + ks * 1024 + mt * 256))[lane];
#pragma unroll
                for (int nt = 0; nt < 4; nt++) {
                    mma16(acc[mt][nt], ah, b0h[nt], b1h[nt]);
                    mma16(acc[mt][nt], ah, b0l[nt], b1l[nt]);
                    mma16(acc[mt][nt], al, b0h[nt], b1h[nt]);
                }
            }
        }
        asm volatile("cp.async.wait_group 0;" ::: "memory");
        __syncthreads();
    }

    // ---- epilogue 1: gate -> z tile (half2 hi/lo, K-pair (zc,zc+8)) ----
#pragma unroll
    for (int mt = 0; mt < 2; mt++) {
        int zc = wm * 32 + mt * 16 + g;
        int s = wm * 16 + mt * 8 + g;
        float bt0 = cb[zc], bg0 = cb[128 + zc];
        float bt8 = cb[zc + 8], bg8 = cb[128 + zc + 8];
#pragma unroll
        for (int nt = 0; nt < 4; nt++) {
            int tc = wn * 32 + nt * 8 + 2 * q;
            float zA0 = ftanh(acc[mt][nt][0] + bt0) * fsig(acc[mt + 2][nt][0] + bg0);
            float zA1 = ftanh(acc[mt][nt][1] + bt0) * fsig(acc[mt + 2][nt][1] + bg0);
            float zB0 = ftanh(acc[mt][nt][2] + bt8) * fsig(acc[mt + 2][nt][2] + bg8);
            float zB1 = ftanh(acc[mt][nt][3] + bt8) * fsig(acc[mt + 2][nt][3] + bg8);
            uint32_t hw, lw;
            mkb(zA0, zB0, hw, lw);
            sw[OZH + s * PT + tc] = hw;
            sw[OZL + s * PT + tc] = lw;
            mkb(zA1, zB1, hw, lw);
            sw[OZH + s * PT + tc + 1] = hw;
            sw[OZL + s * PT + tc + 1] = lw;
        }
    }
    __syncthreads();

    // ---- phase 2: [res;skip][t] = W2 @ z (K permuted), K = 128 ----
#pragma unroll
    for (int mt = 0; mt < 4; mt++)
#pragma unroll
        for (int nt = 0; nt < 4; nt++)
#pragma unroll
            for (int e = 0; e < 4; e++) acc[mt][nt][e] = 0.f;

    for (int kc = 0; kc < 4; kc++) {
        size_t choff = (size_t)(l * 4 + kc) * 8192 + wm * 2048;
        const __half* wh = g_w2h + choff;
        const __half* wl = g_w2l + choff;
#pragma unroll
        for (int ks = 0; ks < 2; ks++) {
            uint32_t base = (uint32_t)(kc * 16 + ks * 8 + q) * PT + tcb;
            uint32_t b0h[4], b0l[4], b1h[4], b1l[4];
#pragma unroll
            for (int nt = 0; nt < 4; nt++) {
                b0h[nt] = sw[OZH + base + nt * 8];
                b1h[nt] = sw[OZH + base + 4 * PT + nt * 8];
                b0l[nt] = sw[OZL + base + nt * 8];
                b1l[nt] = sw[OZL + base + 4 * PT + nt * 8];
            }
#pragma unroll
            for (int mt = 0; mt < 4; mt++) {
                uint4 ah = ((const uint4*)(wh + ks * 1024 + mt * 256))[lane];
                uint4 al = ((const uint4*)(wl + ks * 1024 + mt * 256))[lane];
#pragma unroll
                for (int nt = 0; nt < 4; nt++) {
                    mma16(acc[mt][nt], ah, b0h[nt], b1h[nt]);
                    mma16(acc[mt][nt], ah, b0l[nt], b1l[nt]);
                    mma16(acc[mt][nt], al, b0h[nt], b1h[nt]);
                }
            }
        }
    }

    // ---- epilogue 2: h_out = h_in + res + out_b ; skip += delta ; write packed h ----
#pragma unroll
    for (int mt = 0; mt < 2; mt++) {
        int r0 = wm * 32 + mt * 16 + g;
        float ob0 = ob[r0], ob8 = ob[r0 + 8];
#pragma unroll
        for (int nt = 0; nt < 4; nt++) {
            int tc = wn * 32 + nt * 8 + 2 * q;
            size_t ix = (size_t)r0 * TS + t0 + tc;
            size_t ix8 = ix + (size_t)8 * TS;

            float2 hv = *(const float2*)(hfin + ix);
            float h0 = hv.x + acc[mt][nt][0] + ob0;
            float h1 = hv.y + acc[mt][nt][1] + ob0;
            float2 hv8 = *(const float2*)(hfin + ix8);
            float h8_0 = hv8.x + acc[mt][nt][2] + ob8;
            float h8_1 = hv8.y + acc[mt][nt][3] + ob8;
            *(float2*)(hfout + ix) = make_float2(h0, h1);
            *(float2*)(hfout + ix8) = make_float2(h8_0, h8_1);

            float2 sv = *(const float2*)(skp + ix);
            sv.x += acc[mt + 2][nt][0];
            sv.y += acc[mt + 2][nt][1];
            *(float2*)(skp + ix) = sv;
            float2 sv8 = *(const float2*)(skp + ix8);
            sv8.x += acc[mt + 2][nt][2];
            sv8.y += acc[mt + 2][nt][3];
            *(float2*)(skp + ix8) = sv8;

            // pack adjacent-channel pairs via lane^4 exchange
            float p0 = __shfl_xor_sync(0xffffffffu, h0, 4);
            float p1 = __shfl_xor_sync(0xffffffffu, h1, 4);
            float p8_0 = __shfl_xor_sync(0xffffffffu, h8_0, 4);
            float p8_1 = __shfl_xor_sync(0xffffffffu, h8_1, 4);
            uint32_t hw0, lw0, hw1, lw1;
            int kpair;
            if (!(g & 1)) {
                mkb(h0, p0, hw0, lw0);
                mkb(h1, p1, hw1, lw1);
                kpair = wm * 16 + mt * 8 + (g >> 1);
            } else {
                mkb(p8_0, h8_0, hw0, lw0);
                mkb(p8_1, h8_1, hw1, lw1);
                kpair = wm * 16 + mt * 8 + (g >> 1) + 4;
            }
            size_t px = (size_t)kpair * TS + t0 + tc;
            *(uint2*)(hhout + px) = make_uint2(hw0, hw1);
            *(uint2*)(hlout + px) = make_uint2(lw0, lw1);
        }
    }
}

__global__ void k_out(const float* __restrict__ w2, const float* __restrict__ b2,
                      float* __restrict__ out) {
    int idx = blockIdx.x * blockDim.x + threadIdx.x;  // b*T + t
    int t = idx % TS;
    int b = idx / TS;
    const float* sp = g_skip + (size_t)b * RR * TS + t;
    float a = 0.f;
#pragma unroll 8
    for (int ro = 0; ro < RR; ro++) a += w2[ro] * ftanh(sp[(size_t)ro * TS]);
    out[idx] = a + b2[0];
}

extern "C" void kernel_launch(void* const* d_in, const int* in_sizes, int n_in,
                              void* d_out, int out_size) {
    const float* x       = (const float*)d_in[0];
    const float* input_w = (const float*)d_in[1];
    const float* input_b = (const float*)d_in[2];
    const float* conv_w  = (const float*)d_in[3];
    const float* conv_b  = (const float*)d_in[4];
    const float* out_w   = (const float*)d_in[5];
    const float* out_b   = (const float*)d_in[6];
    const float* out1_w  = (const float*)d_in[7];
    const float* out1_b  = (const float*)d_in[8];
    const float* out2_w  = (const float*)d_in[9];
    const float* out2_b  = (const float*)d_in[10];

    const int SMEM = SMW * 4;  // 56832 bytes -> 2 CTAs/SM
    cudaFuncSetAttribute(k_layer, cudaFuncAttributeMaxDynamicSharedMemorySize, SMEM);

    int n_prep = NL * 12 * 8192 + NL * 4 * 8192;
    k_prep<<<(n_prep + 255) / 256, 256>>>(conv_w, out_w, out1_w);
    k_input<<<(BB * 64 * TS) / 256, 256>>>(x, input_w, input_b, out1_b);

    int par = 0;
    for (int l = 0; l < NL; l++) {
        k_layer<<<dim3(TS / 64, BB), NTHR, SMEM>>>(l, par, conv_b, out_b);
        par ^= 1;
    }
    k_out<<<(BB * TS) / 256, 256>>>(out2_w, out2_b, (float*)d_out);
}